// round 16
// baseline (speedup 1.0000x reference)
#include <cuda_runtime.h>
#include <cuda_fp16.h>
#include <mma.h>
#include <cstdint>

using namespace nvcuda;

// DynamicConv: B=64, CIN=COUT=256, K=4 experts, 3x3 kernel on (L=1024 x 1).
// Width==1 + padding 1 => only kw=1 column contributes: per-batch GEMM
//   C[o,h] = sum_{ci,kh} Wagg[b][o,ci,kh] * x[b][ci,h-1+kh]   (M=256,N=1024,K=768)
// R15: routing folded into prep's mix blocks with ROLLED loops (R12 failed on
//      full unroll -> I$ thrash; lesson applied). Two launches total.
//      Conv unchanged from R14 except bias mixed inline from g_att.

#define BATCH   64
#define CIN     256
#define COUT    256
#define CS      256
#define KEXP    4
#define HIDDEN  64
#define LEN     1024
#define TEMP    30.0f

#define TM      128            // o per CTA
#define TN      128            // h per CTA
#define CCH     64             // ci per K-chunk
#define NCB     (CIN / CCH)    // 4
#define NTILE   (3 * NCB)      // 12

#define ASTR    72             // fp16 A row stride (144 B)
#define BSTR    72             // fp16 B row stride
#define BBSTR   24             // bias tile stride

#define MIXB    96             // mix blocks in prep kernel

// SMEM layout (bytes): A 4 x 18432 | B 2 x 19008
#define SM_ABUF(i) ((uint32_t)(18432u * (i)))
#define SM_B0    73728
#define SM_BBUF(i) ((uint32_t)(SM_B0 + 19008u * (i)))
#define SM_TOTAL (73728 + 2 * 19008)     // 111744
// bias tiles overlay B buf 1 (pre-mainloop only; B1 first written at iter 1)
#define SM_ABH   SM_BBUF(1)
#define SM_BB    (SM_ABH + 6144)

__device__ float g_att[BATCH * KEXP];
// Wagg fp16: [b][kh][cbi][o(256)][ci(64)]
#define WA_BSTRIDE (3 * NCB * COUT * CCH)   // 196608
__device__ __align__(16) __half g_wa[BATCH * WA_BSTRIDE];
// x transposed fp16: [b][h(1024)][ci(256)]
__device__ __align__(16) __half g_xt[(size_t)BATCH * LEN * CIN];

__device__ __forceinline__ uint32_t smem_u32(const void* p) {
    uint32_t a;
    asm("{ .reg .u64 t; cvta.to.shared.u64 t, %1; cvt.u32.u64 %0, t; }" : "=r"(a) : "l"(p));
    return a;
}
__device__ __forceinline__ void cpa16(uint32_t d, const void* s) {
    asm volatile("cp.async.cg.shared.global [%0], [%1], 16;" :: "r"(d), "l"(s));
}
#define CP_COMMIT()  asm volatile("cp.async.commit_group;" ::: "memory")
#define CP_WAIT(n)   asm volatile("cp.async.wait_group %0;" :: "n"(n) : "memory")

// ---------------------------------------------------------------------------
// Kernel 1 (prep): role-split grid.
//   blocks [0, 96)        : routing (redundant per block, ROLLED loops) + mix
//   blocks [96, 96+4096)  : transpose x -> g_xt[b][h][ci] fp16 (64x64 tiles)
// ---------------------------------------------------------------------------
__global__ void prep_kernel(const float* __restrict__ weight,
                            const float* __restrict__ x,
                            const float* __restrict__ cond,
                            const float* __restrict__ w1,
                            const float* __restrict__ w2) {
    __shared__ float s[64][65];
    __shared__ float satt[BATCH][KEXP];
    const int t = threadIdx.x;

    if (blockIdx.x < MIXB) {
        // ---- routing phase 1: hidden = relu(cond @ w1^T), all 64 b ----
        // 4096 dots over 256 threads = 16 each; outer loop ROLLED.
        for (int i = 0; i < 16; ++i) {
            const int idx = t + 256 * i;
            const int b = idx >> 6, h = idx & 63;
            const float4* crow = (const float4*)(cond + b * CS);
            const float4* w1r  = (const float4*)(w1 + h * CS);
            float s0 = 0.0f, s1 = 0.0f;
#pragma unroll 4
            for (int q = 0; q < CS / 4; ++q) {
                float4 c4 = crow[q], w4 = w1r[q];
                s0 = fmaf(c4.x, w4.x, fmaf(c4.y, w4.y, s0));
                s1 = fmaf(c4.z, w4.z, fmaf(c4.w, w4.w, s1));
            }
            s[b][h] = fmaxf(s0 + s1, 0.0f);
        }
        __syncthreads();

        // ---- phase 2: logits (64 b x 4 k), temperature-scaled ----
        {
            const int b = t >> 2, k = t & 3;
            const float* w2r = w2 + k * HIDDEN;
            float lg = 0.0f;
#pragma unroll 4
            for (int h = 0; h < HIDDEN; ++h) lg = fmaf(s[b][h], w2r[h], lg);
            satt[b][k] = lg * (1.0f / TEMP);
        }
        __syncthreads();

        // ---- phase 3: softmax per b ----
        if (t < BATCH) {
            float l0 = satt[t][0], l1 = satt[t][1], l2 = satt[t][2], l3 = satt[t][3];
            float m = fmaxf(fmaxf(l0, l1), fmaxf(l2, l3));
            float e0 = expf(l0 - m), e1 = expf(l1 - m);
            float e2 = expf(l2 - m), e3 = expf(l3 - m);
            float inv = 1.0f / (e0 + e1 + e2 + e3);
            satt[t][0] = e0 * inv; satt[t][1] = e1 * inv;
            satt[t][2] = e2 * inv; satt[t][3] = e3 * inv;
        }
        __syncthreads();
        if (blockIdx.x == 0) g_att[t] = satt[t >> 2][t & 3];   // 256 values

        // ---- phase 4: weight mixing; thread = (kh,cbi,o,8-ci group) ----
        const int idx = blockIdx.x * 256 + t;             // 0 .. 3*4*256*8-1
        const int c8  = idx & 7;
        const int o   = (idx >> 3) & 255;
        const int cbi = (idx >> 11) & 3;
        const int kh  = idx >> 13;
        const int ci0 = cbi * CCH + 8 * c8;

        float w[KEXP][8];
#pragma unroll
        for (int k = 0; k < KEXP; ++k) {
            const float* wp = weight + (((size_t)(k * COUT + o) * CIN + ci0) * 3 + kh) * 3 + 1;
#pragma unroll
            for (int c = 0; c < 8; ++c) w[k][c] = wp[c * 9];
        }

        const size_t obase = (((size_t)kh * NCB + cbi) * COUT + o) * CCH + 8 * c8;
        for (int b = 0; b < BATCH; ++b) {
            float a0 = satt[b][0], a1 = satt[b][1], a2 = satt[b][2], a3 = satt[b][3];
            __half2 hv[4];
#pragma unroll
            for (int p = 0; p < 4; ++p) {
                float v0 = a0 * w[0][2*p]   + a1 * w[1][2*p]   + a2 * w[2][2*p]   + a3 * w[3][2*p];
                float v1 = a0 * w[0][2*p+1] + a1 * w[1][2*p+1] + a2 * w[2][2*p+1] + a3 * w[3][2*p+1];
                hv[p] = __floats2half2_rn(v0, v1);
            }
            *(uint4*)(g_wa + (size_t)b * WA_BSTRIDE + obase) = *(uint4*)hv;
        }
    } else {
        // ---- transpose path: tile (b, 64 h, 64 ci) ----
        const int tb  = blockIdx.x - MIXB;                // 0..4095
        const int b   = tb >> 6;
        const int hti = (tb >> 2) & 15;
        const int cti = tb & 3;
        const int h0  = hti * 64;
        const int ci0 = cti * 64;

        // read: rows = ci (coalesced along h)
#pragma unroll
        for (int q = 0; q < 16; ++q) {
            const int idx = t + q * 256;
            const int r = idx >> 6, c = idx & 63;         // r = ci-local, c = h-local
            s[r][c] = x[((size_t)(b * CIN + ci0 + r)) * LEN + h0 + c];
        }
        __syncthreads();
        // write: rows = h (coalesced along ci); padded smem -> conflict-free
#pragma unroll
        for (int q = 0; q < 16; ++q) {
            const int idx = t + q * 256;
            const int r2 = idx >> 6, c2 = idx & 63;       // r2 = h-local, c2 = ci-local
            g_xt[((size_t)b * LEN + h0 + r2) * CIN + ci0 + c2] = __float2half_rn(s[c2][r2]);
        }
    }
}

// ---------------------------------------------------------------------------
// Kernel 2: wmma fp16 conv. grid (8 h-tiles, 2 o-tiles, 64 b), 256 threads.
// 8 warps, 32x64 warp tiles. 4 A bufs + 2 B bufs, all cp.async, 1 barrier/iter.
// ---------------------------------------------------------------------------
__global__ void __launch_bounds__(256, 2)
conv_kernel(const float* __restrict__ bias, float* __restrict__ out) {
    extern __shared__ char smem[];
    const uint32_t sb = smem_u32(smem);
    const int tid = threadIdx.x;
    const int wid = tid >> 5;
    const int hb  = blockIdx.x * TN;
    const int ob  = blockIdx.y * TM;
    const int b   = blockIdx.z;
    const int wm  = wid >> 1;     // 0..3 -> 32 o-rows
    const int wn  = wid & 1;      // 0..1 -> 64 h-cols

    auto issue_A = [&](int j) {
        const uint32_t bufoff = SM_ABUF(j & 3);
        const int cbi = j / 3;
        const int kh  = j - 3 * cbi;
        const uint4* gs = (const uint4*)(g_wa +
            ((((size_t)b * 3 + kh) * NCB + cbi) * COUT + ob) * CCH);
#pragma unroll
        for (int t = 0; t < 4; ++t) {
            int idx = tid + t * 256;          // 1024 chunks = 128 rows x 8
            int r = idx >> 3, c = idx & 7;
            cpa16(sb + bufoff + r * 144 + c * 16, gs + idx);
        }
    };
    // B tile for chunk cbi2: rows n=0..129 <- g_xt[b][hb-1+n][cbi2*64 .. +64)
    auto issue_B = [&](int cbi2) {
        const uint32_t bufoff = SM_BBUF(cbi2 & 1);
        const __half* gx = g_xt + (size_t)b * LEN * CIN + cbi2 * CCH;
#pragma unroll
        for (int t = 0; t < 5; ++t) {
            int idx = tid + t * 256;          // need 1040 chunks
            if (idx < 1040) {
                int n = idx >> 3, c = idx & 7;
                int h = hb - 1 + n;
                uint32_t d = sb + bufoff + n * 144 + c * 16;
                if ((unsigned)h < (unsigned)LEN)
                    cpa16(d, gx + (size_t)h * CIN + c * 8);
                else
                    *(uint4*)(smem + bufoff + n * 144 + c * 16) = make_uint4(0, 0, 0, 0);
            }
        }
    };

    // prologue groups: g0={A0,B0}, g1={A1}
    issue_A(0);
    issue_B(0);
    CP_COMMIT();
    issue_A(1);
    CP_COMMIT();

    // ---- accumulators + exact-bias K=16 GEMM term (tiles overlay B buf 1) ----
    wmma::fragment<wmma::accumulator, 16, 16, 16, float> acc[2][4];
#pragma unroll
    for (int mt = 0; mt < 2; ++mt)
#pragma unroll
        for (int nt = 0; nt < 4; ++nt) wmma::fill_fragment(acc[mt][nt], 0.0f);

    for (int i = tid; i < 12288 / 4; i += 256)
        ((uint32_t*)(smem + SM_ABH))[i] = 0;
    __syncthreads();
    if (tid < 128) {
        const float* a = g_att + b * KEXP;
        float bm = 0.0f;
#pragma unroll
        for (int k = 0; k < KEXP; ++k) bm = fmaf(a[k], bias[k * COUT + ob + tid], bm);
        __half h = __float2half_rn(bm);
        __half* hA = (__half*)(smem + SM_ABH);
        __half* hB = (__half*)(smem + SM_BB);
        hA[tid * BBSTR + 0] = h;
        hA[tid * BBSTR + 1] = __float2half_rn(bm - __half2float(h));
        hB[tid * BBSTR + 0] = __float2half_rn(1.0f);
        hB[tid * BBSTR + 1] = __float2half_rn(1.0f);
    }
    __syncthreads();
    {
        wmma::fragment<wmma::matrix_a, 16, 16, 16, __half, wmma::row_major> fa;
        wmma::fragment<wmma::matrix_b, 16, 16, 16, __half, wmma::col_major> fb[4];
#pragma unroll
        for (int nt = 0; nt < 4; ++nt)
            wmma::load_matrix_sync(fb[nt],
                (const __half*)(smem + SM_BB) + (wn * 64 + nt * 16) * BBSTR, BBSTR);
#pragma unroll
        for (int mt = 0; mt < 2; ++mt) {
            wmma::load_matrix_sync(fa,
                (const __half*)(smem + SM_ABH) + (wm * 32 + mt * 16) * BBSTR, BBSTR);
#pragma unroll
            for (int nt = 0; nt < 4; ++nt)
                wmma::mma_sync(acc[mt][nt], fa, fb[nt], acc[mt][nt]);
        }
    }

    CP_WAIT(1);                // g0 done: A0 + B0 resident (g1 may pend)
    __syncthreads();           // also: bias-tile reads done before B1 write at j=1

    // ---- mainloop: ONE barrier per iteration ----
    for (int j = 0; j < NTILE; ++j) {
        const int cbi = j / 3;
        const int kh  = j - 3 * cbi;

        if (j + 2 < NTILE) issue_A(j + 2);
        if (kh == 1 && cbi + 1 < NCB) issue_B(cbi + 1);   // no reader of buf
                                                          // (cbi+1)&1 in window
        CP_COMMIT();                 // group g_{j+2}
        CP_WAIT(2);                  // groups <= g_j done: A(j), B(cbi) resident
        __syncthreads();

        const __half* A  = (const __half*)(smem + SM_ABUF(j & 3));
        const __half* Bp = (const __half*)(smem + SM_BBUF(cbi & 1));

#pragma unroll
        for (int ks = 0; ks < 4; ++ks) {
            wmma::fragment<wmma::matrix_a, 16, 16, 16, __half, wmma::row_major> fa[2];
            wmma::fragment<wmma::matrix_b, 16, 16, 16, __half, wmma::col_major> fb[4];
#pragma unroll
            for (int mt = 0; mt < 2; ++mt)
                wmma::load_matrix_sync(fa[mt], A + (wm * 32 + mt * 16) * ASTR + ks * 16, ASTR);
#pragma unroll
            for (int nt = 0; nt < 4; ++nt)
                wmma::load_matrix_sync(fb[nt], Bp + (wn * 64 + nt * 16 + kh) * BSTR + ks * 16, BSTR);
#pragma unroll
            for (int mt = 0; mt < 2; ++mt)
#pragma unroll
                for (int nt = 0; nt < 4; ++nt)
                    wmma::mma_sync(acc[mt][nt], fa[mt], fb[nt], acc[mt][nt]);
        }
        // no trailing barrier: 4-deep A ring + 2-deep B ring make next issues safe
    }

    // ---- epilogue: bias already in acc; direct global store ----
    float* op = out + ((size_t)(b * COUT + ob + wm * 32)) * LEN + hb + wn * 64;
#pragma unroll
    for (int mt = 0; mt < 2; ++mt)
#pragma unroll
        for (int nt = 0; nt < 4; ++nt)
            wmma::store_matrix_sync(op + (size_t)mt * 16 * LEN + nt * 16,
                                    acc[mt][nt], LEN, wmma::mem_row_major);
}

// ---------------------------------------------------------------------------
extern "C" void kernel_launch(void* const* d_in, const int* in_sizes, int n_in,
                              void* d_out, int out_size) {
    const float* x      = (const float*)d_in[0];   // (64,256,1024,1)
    const float* cond   = (const float*)d_in[1];   // (64,256)
    const float* w1     = (const float*)d_in[2];   // (64,256)
    const float* w2     = (const float*)d_in[3];   // (4,64)
    const float* weight = (const float*)d_in[4];   // (4,256,256,3,3)
    const float* bias   = (const float*)d_in[5];   // (4,256)
    float* out = (float*)d_out;                    // (64,256,1024,1)

    static int attr_set = 0;
    if (!attr_set) {
        cudaFuncSetAttribute(conv_kernel,
                             cudaFuncAttributeMaxDynamicSharedMemorySize, SM_TOTAL);
        attr_set = 1;
    }

    prep_kernel<<<MIXB + BATCH * 16 * 4, 256>>>(weight, x, cond, w1, w2);
    conv_kernel<<<dim3(LEN / TN, COUT / TM, BATCH), 256, SM_TOTAL>>>(bias, out);
}